// round 1
// baseline (speedup 1.0000x reference)
#include <cuda_runtime.h>
#include <math.h>

#define BSZ   2048
#define NNODE 63
#define NROWS (BSZ * NNODE)   // 129024

// ---- scratch (device globals; no runtime allocation) ----
__device__ float g_X1[(size_t)NROWS * 256];     // [row][0:64 op_vec |64:128 c1 |128:192 c2 |192:256 bm]
__device__ float g_rep[(size_t)NROWS * 128];    // per-node representation
__device__ float g_h[(size_t)65536 * 256];      // intermediate h for the widest level (l=5)

// ============================================================
// Embed (small): X1[:,0:192] = [op|extra]@W_op+b ; cond1@W_pred+b ; cond2@W_pred+b
// grid 2016 x 256 threads, 64 rows/CTA
// ============================================================
__global__ void __launch_bounds__(256) embed_small_kernel(
    const float* __restrict__ op, const float* __restrict__ extra,
    const float* __restrict__ c1, const float* __restrict__ c2,
    const float* __restrict__ Wop, const float* __restrict__ bop,
    const float* __restrict__ Wpred, const float* __restrict__ bpred)
{
    __shared__ float sIn[64][65];
    __shared__ float sW[64][64];
    int tid = threadIdx.x;
    int r0  = blockIdx.x * 64;
    int ty  = tid >> 4, tx = tid & 15;

    for (int seg = 0; seg < 3; ++seg) {
        if (seg == 0) {
            for (int idx = tid; idx < 64 * 64; idx += 256) {
                int row = idx >> 6, c = idx & 63;
                float v = (c < 32) ? op[(size_t)(r0 + row) * 32 + c]
                                   : extra[(size_t)(r0 + row) * 32 + (c - 32)];
                sIn[row][c] = v;
            }
        } else {
            const float* src = (seg == 1) ? c1 : c2;
            for (int idx = tid; idx < 64 * 64; idx += 256) {
                int row = idx >> 6, c = idx & 63;
                sIn[row][c] = src[(size_t)(r0 + row) * 64 + c];
            }
        }
        const float* W = (seg == 0) ? Wop : Wpred;
        for (int idx = tid; idx < 64 * 64; idx += 256)
            sW[idx >> 6][idx & 63] = W[idx];
        __syncthreads();

        float acc[4][4] = {};
        #pragma unroll 8
        for (int k = 0; k < 64; k++) {
            float a[4];
            #pragma unroll
            for (int i = 0; i < 4; i++) a[i] = sIn[ty * 4 + i][k];
            float4 w = *(const float4*)&sW[k][tx * 4];
            #pragma unroll
            for (int i = 0; i < 4; i++) {
                acc[i][0] += a[i] * w.x; acc[i][1] += a[i] * w.y;
                acc[i][2] += a[i] * w.z; acc[i][3] += a[i] * w.w;
            }
        }
        const float* bias = (seg == 0) ? bop : bpred;
        #pragma unroll
        for (int i = 0; i < 4; i++) {
            int row = r0 + ty * 4 + i;
            #pragma unroll
            for (int q = 0; q < 4; q++) {
                int c = tx * 4 + q;
                g_X1[(size_t)row * 256 + seg * 64 + c] = acc[i][q] + bias[c];
            }
        }
        __syncthreads();
    }
}

// ============================================================
// Embed (bitmap): X1[:,192:256] = (bitmap @ W_bm + b_bm) * has_cond
// grid 1008 x 256 threads, 128 rows/CTA, K=1000 in chunks of 8
// ============================================================
__global__ void __launch_bounds__(256) embed_bm_kernel(
    const float* __restrict__ bm, const float* __restrict__ hc,
    const float* __restrict__ Wbm, const float* __restrict__ bbm)
{
    __shared__ float sA[8][132];   // transposed: sA[kk][row]
    __shared__ float sB[8][64];
    int tid = threadIdx.x;
    int r0  = blockIdx.x * 128;
    int ty  = tid >> 4, tx = tid & 15;   // rows ty*8..+7, cols tx*4..+3
    int lrow = tid >> 1, lf = tid & 1;
    const float* srcrow = bm + (size_t)(r0 + lrow) * 1000 + lf * 4;

    float acc[8][4] = {};
    for (int k0 = 0; k0 < 1000; k0 += 8) {
        float4 v = *(const float4*)(srcrow + k0);
        sA[lf * 4 + 0][lrow] = v.x; sA[lf * 4 + 1][lrow] = v.y;
        sA[lf * 4 + 2][lrow] = v.z; sA[lf * 4 + 3][lrow] = v.w;
        if (tid < 128) {
            int kk = tid >> 4, c4 = tid & 15;
            *((float4*)&sB[kk][c4 * 4]) = *(const float4*)&Wbm[(size_t)(k0 + kk) * 64 + c4 * 4];
        }
        __syncthreads();
        #pragma unroll
        for (int kk = 0; kk < 8; kk++) {
            float4 a0 = *(const float4*)&sA[kk][ty * 8];
            float4 a1 = *(const float4*)&sA[kk][ty * 8 + 4];
            float  a[8] = {a0.x, a0.y, a0.z, a0.w, a1.x, a1.y, a1.z, a1.w};
            float4 w  = *(const float4*)&sB[kk][tx * 4];
            #pragma unroll
            for (int i = 0; i < 8; i++) {
                acc[i][0] += a[i] * w.x; acc[i][1] += a[i] * w.y;
                acc[i][2] += a[i] * w.z; acc[i][3] += a[i] * w.w;
            }
        }
        __syncthreads();
    }
    #pragma unroll
    for (int i = 0; i < 8; i++) {
        int row = r0 + ty * 8 + i;
        float h = hc[row];
        #pragma unroll
        for (int q = 0; q < 4; q++) {
            int c = tx * 4 + q;
            g_X1[(size_t)row * 256 + 192 + c] = (acc[i][q] + bbm[c]) * h;
        }
    }
}

// ============================================================
// Tree GEMM1: h = relu( [X1_row | rep(left) | rep(right)] @ W_r1 + b_r1 )
// per level: M = 2048*2^l rows, K=512, N=256. Tile 64x256, micro 8x8.
// Leaf children (index >= 63) contribute zeros.
// ============================================================
__global__ void __launch_bounds__(256) tree_g1_kernel(
    const float* __restrict__ W1, const float* __restrict__ b1, int lvl)
{
    __shared__ float sA[64][17];
    __shared__ float sW[16][256];
    int tid = threadIdx.x;
    int m0  = blockIdx.x * 64;
    int ty  = tid >> 5, tx = tid & 31;   // rows ty*8..+7, cols {tx*4..+3, 128+tx*4..+3}
    int nl  = 1 << lvl;

    // per-thread A-tile loader source pointers
    int lrow = tid >> 2, lf = tid & 3;
    int lm = m0 + lrow;
    int lb = lm >> lvl;
    int lj = (nl - 1) + (lm & (nl - 1));
    const float* srcX = g_X1 + (size_t)(lb * 63 + lj) * 256;
    int cl = 2 * lj + 1, cr = 2 * lj + 2;
    const float* srcL = (cl < 63) ? g_rep + (size_t)(lb * 63 + cl) * 128 : 0;
    const float* srcR = (cr < 63) ? g_rep + (size_t)(lb * 63 + cr) * 128 : 0;

    float acc[8][8] = {};
    for (int k0 = 0; k0 < 512; k0 += 16) {
        float4 v = make_float4(0.f, 0.f, 0.f, 0.f);
        int kofs = k0 + lf * 4;
        if (k0 < 256)            v = *(const float4*)(srcX + kofs);
        else if (k0 < 384) { if (srcL) v = *(const float4*)(srcL + (kofs - 256)); }
        else               { if (srcR) v = *(const float4*)(srcR + (kofs - 384)); }
        sA[lrow][lf * 4 + 0] = v.x; sA[lrow][lf * 4 + 1] = v.y;
        sA[lrow][lf * 4 + 2] = v.z; sA[lrow][lf * 4 + 3] = v.w;

        int kk = tid >> 4, c4 = tid & 15;
        const float* wrow = W1 + (size_t)(k0 + kk) * 256;
        #pragma unroll
        for (int q = 0; q < 4; q++)
            *((float4*)&sW[kk][(c4 + 16 * q) * 4]) = *(const float4*)(wrow + (c4 + 16 * q) * 4);
        __syncthreads();

        #pragma unroll
        for (int k = 0; k < 16; k++) {
            float a[8];
            #pragma unroll
            for (int i = 0; i < 8; i++) a[i] = sA[ty * 8 + i][k];
            float4 w0 = *(const float4*)&sW[k][tx * 4];
            float4 w1 = *(const float4*)&sW[k][128 + tx * 4];
            #pragma unroll
            for (int i = 0; i < 8; i++) {
                acc[i][0] += a[i] * w0.x; acc[i][1] += a[i] * w0.y;
                acc[i][2] += a[i] * w0.z; acc[i][3] += a[i] * w0.w;
                acc[i][4] += a[i] * w1.x; acc[i][5] += a[i] * w1.y;
                acc[i][6] += a[i] * w1.z; acc[i][7] += a[i] * w1.w;
            }
        }
        __syncthreads();
    }
    float bl0[4], bl1[4];
    #pragma unroll
    for (int q = 0; q < 4; q++) { bl0[q] = b1[tx * 4 + q]; bl1[q] = b1[128 + tx * 4 + q]; }
    #pragma unroll
    for (int i = 0; i < 8; i++) {
        float* dst = g_h + (size_t)(m0 + ty * 8 + i) * 256;
        #pragma unroll
        for (int q = 0; q < 4; q++) {
            dst[tx * 4 + q]       = fmaxf(acc[i][q]     + bl0[q], 0.f);
            dst[128 + tx * 4 + q] = fmaxf(acc[i][q + 4] + bl1[q], 0.f);
        }
    }
}

// ============================================================
// Tree GEMM2: rep = relu( h @ W_r2 + b_r2 )   K=256, N=128. Tile 64x128, micro 8x4.
// ============================================================
__global__ void __launch_bounds__(256) tree_g2_kernel(
    const float* __restrict__ W2, const float* __restrict__ b2, int lvl)
{
    __shared__ float sH[64][17];
    __shared__ float sW[16][128];
    int tid = threadIdx.x;
    int m0  = blockIdx.x * 64;
    int ty  = tid >> 5, tx = tid & 31;
    int nl  = 1 << lvl;
    int lrow = tid >> 2, lf = tid & 3;
    const float* srcH = g_h + (size_t)(m0 + lrow) * 256;

    float acc[8][4] = {};
    for (int k0 = 0; k0 < 256; k0 += 16) {
        float4 v = *(const float4*)(srcH + k0 + lf * 4);
        sH[lrow][lf * 4 + 0] = v.x; sH[lrow][lf * 4 + 1] = v.y;
        sH[lrow][lf * 4 + 2] = v.z; sH[lrow][lf * 4 + 3] = v.w;
        int kk = tid >> 4, c4 = tid & 15;
        const float* wrow = W2 + (size_t)(k0 + kk) * 128;
        *((float4*)&sW[kk][c4 * 4])      = *(const float4*)(wrow + c4 * 4);
        *((float4*)&sW[kk][64 + c4 * 4]) = *(const float4*)(wrow + 64 + c4 * 4);
        __syncthreads();
        #pragma unroll
        for (int k = 0; k < 16; k++) {
            float a[8];
            #pragma unroll
            for (int i = 0; i < 8; i++) a[i] = sH[ty * 8 + i][k];
            float4 w = *(const float4*)&sW[k][tx * 4];
            #pragma unroll
            for (int i = 0; i < 8; i++) {
                acc[i][0] += a[i] * w.x; acc[i][1] += a[i] * w.y;
                acc[i][2] += a[i] * w.z; acc[i][3] += a[i] * w.w;
            }
        }
        __syncthreads();
    }
    float bl[4];
    #pragma unroll
    for (int q = 0; q < 4; q++) bl[q] = b2[tx * 4 + q];
    #pragma unroll
    for (int i = 0; i < 8; i++) {
        int m = m0 + ty * 8 + i;
        int b = m >> lvl;
        int j = (nl - 1) + (m & (nl - 1));
        float* dst = g_rep + (size_t)(b * 63 + j) * 128;
        #pragma unroll
        for (int q = 0; q < 4; q++)
            dst[tx * 4 + q] = fmaxf(acc[i][q] + bl[q], 0.f);
    }
}

// ============================================================
// Heads: cost/card = sigmoid(MLP3(root)).  1 block / batch row, 128 threads
// (threads 0..63 -> cost head, 64..127 -> card head)
// ============================================================
__global__ void __launch_bounds__(128) heads_kernel(
    const float* __restrict__ Wc1, const float* __restrict__ bc1,
    const float* __restrict__ Wc2, const float* __restrict__ bc2,
    const float* __restrict__ Wc3, const float* __restrict__ bc3,
    const float* __restrict__ Wd1, const float* __restrict__ bd1,
    const float* __restrict__ Wd2, const float* __restrict__ bd2,
    const float* __restrict__ Wd3, const float* __restrict__ bd3,
    float* __restrict__ out)
{
    __shared__ float sroot[128];
    __shared__ float sh1[128];
    __shared__ float sprod[128];
    int b = blockIdx.x, t = threadIdx.x;
    sroot[t] = g_rep[(size_t)(b * 63) * 128 + t];
    __syncthreads();

    int head = t >> 6, c = t & 63;
    const float* W1 = head ? Wd1 : Wc1; const float* B1 = head ? bd1 : bc1;
    const float* W2 = head ? Wd2 : Wc2; const float* B2 = head ? bd2 : bc2;
    const float* W3 = head ? Wd3 : Wc3; const float* B3 = head ? bd3 : bc3;

    float h = B1[c];
    #pragma unroll 8
    for (int k = 0; k < 128; k++) h += sroot[k] * W1[k * 64 + c];
    sh1[t] = fmaxf(h, 0.f);
    __syncthreads();

    float h2 = B2[c];
    #pragma unroll 8
    for (int k = 0; k < 64; k++) h2 += sh1[head * 64 + k] * W2[k * 64 + c];
    h2 = fmaxf(h2, 0.f);
    sprod[t] = h2 * W3[c];
    __syncthreads();

    if (c == 0) {
        float s = B3[0];
        #pragma unroll 8
        for (int k = 0; k < 64; k++) s += sprod[head * 64 + k];
        out[head * BSZ + b] = 1.f / (1.f + expf(-s));
    }
}

// ============================================================
// launch
// ============================================================
extern "C" void kernel_launch(void* const* d_in, const int* in_sizes, int n_in,
                              void* d_out, int out_size)
{
    const float* op      = (const float*)d_in[0];
    const float* extra   = (const float*)d_in[1];
    const float* cond1   = (const float*)d_in[2];
    const float* cond2   = (const float*)d_in[3];
    const float* bitmap  = (const float*)d_in[4];
    const float* hascond = (const float*)d_in[5];
    const float* W_op  = (const float*)d_in[6];   const float* b_op  = (const float*)d_in[7];
    const float* W_pr  = (const float*)d_in[8];   const float* b_pr  = (const float*)d_in[9];
    const float* W_bm  = (const float*)d_in[10];  const float* b_bm  = (const float*)d_in[11];
    const float* W_r1  = (const float*)d_in[12];  const float* b_r1  = (const float*)d_in[13];
    const float* W_r2  = (const float*)d_in[14];  const float* b_r2  = (const float*)d_in[15];
    const float* W_c1  = (const float*)d_in[16];  const float* b_c1  = (const float*)d_in[17];
    const float* W_c2  = (const float*)d_in[18];  const float* b_c2  = (const float*)d_in[19];
    const float* W_c3  = (const float*)d_in[20];  const float* b_c3  = (const float*)d_in[21];
    const float* W_d1  = (const float*)d_in[22];  const float* b_d1  = (const float*)d_in[23];
    const float* W_d2  = (const float*)d_in[24];  const float* b_d2  = (const float*)d_in[25];
    const float* W_d3  = (const float*)d_in[26];  const float* b_d3  = (const float*)d_in[27];

    embed_small_kernel<<<NROWS / 64, 256>>>(op, extra, cond1, cond2, W_op, b_op, W_pr, b_pr);
    embed_bm_kernel<<<NROWS / 128, 256>>>(bitmap, hascond, W_bm, b_bm);

    for (int l = 5; l >= 0; --l) {
        int M = BSZ << l;   // B * 2^l rows at this level
        tree_g1_kernel<<<M / 64, 256>>>(W_r1, b_r1, l);
        tree_g2_kernel<<<M / 64, 256>>>(W_r2, b_r2, l);
    }

    heads_kernel<<<BSZ, 128>>>(W_c1, b_c1, W_c2, b_c2, W_c3, b_c3,
                               W_d1, b_d1, W_d2, b_d2, W_d3, b_d3,
                               (float*)d_out);
}

// round 2
// speedup vs baseline: 1.0021x; 1.0021x over previous
#include <cuda_runtime.h>
#include <math.h>

#define BSZ   2048
#define NNODE 63
#define NROWS (BSZ * NNODE)   // 129024

// ---- scratch (device globals; no runtime allocation) ----
__device__ float g_X1[(size_t)NROWS * 256];     // [row][0:64 op_vec |64:128 c1 |128:192 c2 |192:256 bm]
__device__ float g_rep[(size_t)NROWS * 128];    // per-node representation
__device__ float g_h[(size_t)65536 * 256];      // intermediate h for the widest level (l=5)

// ============================================================
// Embed (small): X1[:,0:192] = [op|extra]@W_op+b ; cond1@W_pred+b ; cond2@W_pred+b
// grid 2016 x 256 threads, 64 rows/CTA
// ============================================================
__global__ void __launch_bounds__(256) embed_small_kernel(
    const float* __restrict__ op, const float* __restrict__ extra,
    const float* __restrict__ c1, const float* __restrict__ c2,
    const float* __restrict__ Wop, const float* __restrict__ bop,
    const float* __restrict__ Wpred, const float* __restrict__ bpred)
{
    __shared__ float sIn[64][65];
    __shared__ float sW[64][64];
    int tid = threadIdx.x;
    int r0  = blockIdx.x * 64;
    int ty  = tid >> 4, tx = tid & 15;

    for (int seg = 0; seg < 3; ++seg) {
        if (seg == 0) {
            for (int idx = tid; idx < 64 * 64; idx += 256) {
                int row = idx >> 6, c = idx & 63;
                float v = (c < 32) ? op[(size_t)(r0 + row) * 32 + c]
                                   : extra[(size_t)(r0 + row) * 32 + (c - 32)];
                sIn[row][c] = v;
            }
        } else {
            const float* src = (seg == 1) ? c1 : c2;
            for (int idx = tid; idx < 64 * 64; idx += 256) {
                int row = idx >> 6, c = idx & 63;
                sIn[row][c] = src[(size_t)(r0 + row) * 64 + c];
            }
        }
        const float* W = (seg == 0) ? Wop : Wpred;
        for (int idx = tid; idx < 64 * 64; idx += 256)
            sW[idx >> 6][idx & 63] = W[idx];
        __syncthreads();

        float acc[4][4] = {};
        #pragma unroll 8
        for (int k = 0; k < 64; k++) {
            float a[4];
            #pragma unroll
            for (int i = 0; i < 4; i++) a[i] = sIn[ty * 4 + i][k];
            float4 w = *(const float4*)&sW[k][tx * 4];
            #pragma unroll
            for (int i = 0; i < 4; i++) {
                acc[i][0] += a[i] * w.x; acc[i][1] += a[i] * w.y;
                acc[i][2] += a[i] * w.z; acc[i][3] += a[i] * w.w;
            }
        }
        const float* bias = (seg == 0) ? bop : bpred;
        #pragma unroll
        for (int i = 0; i < 4; i++) {
            int row = r0 + ty * 4 + i;
            #pragma unroll
            for (int q = 0; q < 4; q++) {
                int c = tx * 4 + q;
                g_X1[(size_t)row * 256 + seg * 64 + c] = acc[i][q] + bias[c];
            }
        }
        __syncthreads();
    }
}

// ============================================================
// Embed (bitmap): X1[:,192:256] = (bitmap @ W_bm + b_bm) * has_cond
// grid 1008 x 256 threads, 128 rows/CTA, K=1000 in chunks of 8
// ============================================================
__global__ void __launch_bounds__(256) embed_bm_kernel(
    const float* __restrict__ bm, const float* __restrict__ hc,
    const float* __restrict__ Wbm, const float* __restrict__ bbm)
{
    __shared__ float sA[8][132];   // transposed: sA[kk][row]
    __shared__ float sB[8][64];
    int tid = threadIdx.x;
    int r0  = blockIdx.x * 128;
    int ty  = tid >> 4, tx = tid & 15;   // rows ty*8..+7, cols tx*4..+3
    int lrow = tid >> 1, lf = tid & 1;
    const float* srcrow = bm + (size_t)(r0 + lrow) * 1000 + lf * 4;

    float acc[8][4] = {};
    for (int k0 = 0; k0 < 1000; k0 += 8) {
        float4 v = *(const float4*)(srcrow + k0);
        sA[lf * 4 + 0][lrow] = v.x; sA[lf * 4 + 1][lrow] = v.y;
        sA[lf * 4 + 2][lrow] = v.z; sA[lf * 4 + 3][lrow] = v.w;
        if (tid < 128) {
            int kk = tid >> 4, c4 = tid & 15;
            *((float4*)&sB[kk][c4 * 4]) = *(const float4*)&Wbm[(size_t)(k0 + kk) * 64 + c4 * 4];
        }
        __syncthreads();
        #pragma unroll
        for (int kk = 0; kk < 8; kk++) {
            float4 a0 = *(const float4*)&sA[kk][ty * 8];
            float4 a1 = *(const float4*)&sA[kk][ty * 8 + 4];
            float  a[8] = {a0.x, a0.y, a0.z, a0.w, a1.x, a1.y, a1.z, a1.w};
            float4 w  = *(const float4*)&sB[kk][tx * 4];
            #pragma unroll
            for (int i = 0; i < 8; i++) {
                acc[i][0] += a[i] * w.x; acc[i][1] += a[i] * w.y;
                acc[i][2] += a[i] * w.z; acc[i][3] += a[i] * w.w;
            }
        }
        __syncthreads();
    }
    #pragma unroll
    for (int i = 0; i < 8; i++) {
        int row = r0 + ty * 8 + i;
        float h = hc[row];
        #pragma unroll
        for (int q = 0; q < 4; q++) {
            int c = tx * 4 + q;
            g_X1[(size_t)row * 256 + 192 + c] = (acc[i][q] + bbm[c]) * h;
        }
    }
}

// ============================================================
// Tree GEMM1: h = relu( [X1_row | rep(left) | rep(right)] @ W_r1 + b_r1 )
// per level: M = 2048*2^l rows, K=512, N=256. Tile 64x256, micro 8x8.
// Leaf children (index >= 63) contribute zeros.
// ============================================================
__global__ void __launch_bounds__(256) tree_g1_kernel(
    const float* __restrict__ W1, const float* __restrict__ b1, int lvl)
{
    __shared__ float sA[64][17];
    __shared__ float sW[16][256];
    int tid = threadIdx.x;
    int m0  = blockIdx.x * 64;
    int ty  = tid >> 5, tx = tid & 31;   // rows ty*8..+7, cols {tx*4..+3, 128+tx*4..+3}
    int nl  = 1 << lvl;

    // per-thread A-tile loader source pointers
    int lrow = tid >> 2, lf = tid & 3;
    int lm = m0 + lrow;
    int lb = lm >> lvl;
    int lj = (nl - 1) + (lm & (nl - 1));
    const float* srcX = g_X1 + (size_t)(lb * 63 + lj) * 256;
    int cl = 2 * lj + 1, cr = 2 * lj + 2;
    const float* srcL = (cl < 63) ? g_rep + (size_t)(lb * 63 + cl) * 128 : 0;
    const float* srcR = (cr < 63) ? g_rep + (size_t)(lb * 63 + cr) * 128 : 0;

    float acc[8][8] = {};
    for (int k0 = 0; k0 < 512; k0 += 16) {
        float4 v = make_float4(0.f, 0.f, 0.f, 0.f);
        int kofs = k0 + lf * 4;
        if (k0 < 256)            v = *(const float4*)(srcX + kofs);
        else if (k0 < 384) { if (srcL) v = *(const float4*)(srcL + (kofs - 256)); }
        else               { if (srcR) v = *(const float4*)(srcR + (kofs - 384)); }
        sA[lrow][lf * 4 + 0] = v.x; sA[lrow][lf * 4 + 1] = v.y;
        sA[lrow][lf * 4 + 2] = v.z; sA[lrow][lf * 4 + 3] = v.w;

        int kk = tid >> 4, c4 = tid & 15;
        const float* wrow = W1 + (size_t)(k0 + kk) * 256;
        #pragma unroll
        for (int q = 0; q < 4; q++)
            *((float4*)&sW[kk][(c4 + 16 * q) * 4]) = *(const float4*)(wrow + (c4 + 16 * q) * 4);
        __syncthreads();

        #pragma unroll
        for (int k = 0; k < 16; k++) {
            float a[8];
            #pragma unroll
            for (int i = 0; i < 8; i++) a[i] = sA[ty * 8 + i][k];
            float4 w0 = *(const float4*)&sW[k][tx * 4];
            float4 w1 = *(const float4*)&sW[k][128 + tx * 4];
            #pragma unroll
            for (int i = 0; i < 8; i++) {
                acc[i][0] += a[i] * w0.x; acc[i][1] += a[i] * w0.y;
                acc[i][2] += a[i] * w0.z; acc[i][3] += a[i] * w0.w;
                acc[i][4] += a[i] * w1.x; acc[i][5] += a[i] * w1.y;
                acc[i][6] += a[i] * w1.z; acc[i][7] += a[i] * w1.w;
            }
        }
        __syncthreads();
    }
    float bl0[4], bl1[4];
    #pragma unroll
    for (int q = 0; q < 4; q++) { bl0[q] = b1[tx * 4 + q]; bl1[q] = b1[128 + tx * 4 + q]; }
    #pragma unroll
    for (int i = 0; i < 8; i++) {
        float* dst = g_h + (size_t)(m0 + ty * 8 + i) * 256;
        #pragma unroll
        for (int q = 0; q < 4; q++) {
            dst[tx * 4 + q]       = fmaxf(acc[i][q]     + bl0[q], 0.f);
            dst[128 + tx * 4 + q] = fmaxf(acc[i][q + 4] + bl1[q], 0.f);
        }
    }
}

// ============================================================
// Tree GEMM2: rep = relu( h @ W_r2 + b_r2 )   K=256, N=128. Tile 64x128, micro 8x4.
// ============================================================
__global__ void __launch_bounds__(256) tree_g2_kernel(
    const float* __restrict__ W2, const float* __restrict__ b2, int lvl)
{
    __shared__ float sH[64][17];
    __shared__ float sW[16][128];
    int tid = threadIdx.x;
    int m0  = blockIdx.x * 64;
    int ty  = tid >> 5, tx = tid & 31;
    int nl  = 1 << lvl;
    int lrow = tid >> 2, lf = tid & 3;
    const float* srcH = g_h + (size_t)(m0 + lrow) * 256;

    float acc[8][4] = {};
    for (int k0 = 0; k0 < 256; k0 += 16) {
        float4 v = *(const float4*)(srcH + k0 + lf * 4);
        sH[lrow][lf * 4 + 0] = v.x; sH[lrow][lf * 4 + 1] = v.y;
        sH[lrow][lf * 4 + 2] = v.z; sH[lrow][lf * 4 + 3] = v.w;
        int kk = tid >> 4, c4 = tid & 15;
        const float* wrow = W2 + (size_t)(k0 + kk) * 128;
        *((float4*)&sW[kk][c4 * 4])      = *(const float4*)(wrow + c4 * 4);
        *((float4*)&sW[kk][64 + c4 * 4]) = *(const float4*)(wrow + 64 + c4 * 4);
        __syncthreads();
        #pragma unroll
        for (int k = 0; k < 16; k++) {
            float a[8];
            #pragma unroll
            for (int i = 0; i < 8; i++) a[i] = sH[ty * 8 + i][k];
            float4 w = *(const float4*)&sW[k][tx * 4];
            #pragma unroll
            for (int i = 0; i < 8; i++) {
                acc[i][0] += a[i] * w.x; acc[i][1] += a[i] * w.y;
                acc[i][2] += a[i] * w.z; acc[i][3] += a[i] * w.w;
            }
        }
        __syncthreads();
    }
    float bl[4];
    #pragma unroll
    for (int q = 0; q < 4; q++) bl[q] = b2[tx * 4 + q];
    #pragma unroll
    for (int i = 0; i < 8; i++) {
        int m = m0 + ty * 8 + i;
        int b = m >> lvl;
        int j = (nl - 1) + (m & (nl - 1));
        float* dst = g_rep + (size_t)(b * 63 + j) * 128;
        #pragma unroll
        for (int q = 0; q < 4; q++)
            dst[tx * 4 + q] = fmaxf(acc[i][q] + bl[q], 0.f);
    }
}

// ============================================================
// Heads: cost/card = sigmoid(MLP3(root)).  1 block / batch row, 128 threads
// (threads 0..63 -> cost head, 64..127 -> card head)
// ============================================================
__global__ void __launch_bounds__(128) heads_kernel(
    const float* __restrict__ Wc1, const float* __restrict__ bc1,
    const float* __restrict__ Wc2, const float* __restrict__ bc2,
    const float* __restrict__ Wc3, const float* __restrict__ bc3,
    const float* __restrict__ Wd1, const float* __restrict__ bd1,
    const float* __restrict__ Wd2, const float* __restrict__ bd2,
    const float* __restrict__ Wd3, const float* __restrict__ bd3,
    float* __restrict__ out)
{
    __shared__ float sroot[128];
    __shared__ float sh1[128];
    __shared__ float sprod[128];
    int b = blockIdx.x, t = threadIdx.x;
    sroot[t] = g_rep[(size_t)(b * 63) * 128 + t];
    __syncthreads();

    int head = t >> 6, c = t & 63;
    const float* W1 = head ? Wd1 : Wc1; const float* B1 = head ? bd1 : bc1;
    const float* W2 = head ? Wd2 : Wc2; const float* B2 = head ? bd2 : bc2;
    const float* W3 = head ? Wd3 : Wc3; const float* B3 = head ? bd3 : bc3;

    float h = B1[c];
    #pragma unroll 8
    for (int k = 0; k < 128; k++) h += sroot[k] * W1[k * 64 + c];
    sh1[t] = fmaxf(h, 0.f);
    __syncthreads();

    float h2 = B2[c];
    #pragma unroll 8
    for (int k = 0; k < 64; k++) h2 += sh1[head * 64 + k] * W2[k * 64 + c];
    h2 = fmaxf(h2, 0.f);
    sprod[t] = h2 * W3[c];
    __syncthreads();

    if (c == 0) {
        float s = B3[0];
        #pragma unroll 8
        for (int k = 0; k < 64; k++) s += sprod[head * 64 + k];
        out[head * BSZ + b] = 1.f / (1.f + expf(-s));
    }
}

// ============================================================
// launch
// ============================================================
extern "C" void kernel_launch(void* const* d_in, const int* in_sizes, int n_in,
                              void* d_out, int out_size)
{
    const float* op      = (const float*)d_in[0];
    const float* extra   = (const float*)d_in[1];
    const float* cond1   = (const float*)d_in[2];
    const float* cond2   = (const float*)d_in[3];
    const float* bitmap  = (const float*)d_in[4];
    const float* hascond = (const float*)d_in[5];
    const float* W_op  = (const float*)d_in[6];   const float* b_op  = (const float*)d_in[7];
    const float* W_pr  = (const float*)d_in[8];   const float* b_pr  = (const float*)d_in[9];
    const float* W_bm  = (const float*)d_in[10];  const float* b_bm  = (const float*)d_in[11];
    const float* W_r1  = (const float*)d_in[12];  const float* b_r1  = (const float*)d_in[13];
    const float* W_r2  = (const float*)d_in[14];  const float* b_r2  = (const float*)d_in[15];
    const float* W_c1  = (const float*)d_in[16];  const float* b_c1  = (const float*)d_in[17];
    const float* W_c2  = (const float*)d_in[18];  const float* b_c2  = (const float*)d_in[19];
    const float* W_c3  = (const float*)d_in[20];  const float* b_c3  = (const float*)d_in[21];
    const float* W_d1  = (const float*)d_in[22];  const float* b_d1  = (const float*)d_in[23];
    const float* W_d2  = (const float*)d_in[24];  const float* b_d2  = (const float*)d_in[25];
    const float* W_d3  = (const float*)d_in[26];  const float* b_d3  = (const float*)d_in[27];

    embed_small_kernel<<<NROWS / 64, 256>>>(op, extra, cond1, cond2, W_op, b_op, W_pr, b_pr);
    embed_bm_kernel<<<NROWS / 128, 256>>>(bitmap, hascond, W_bm, b_bm);

    for (int l = 5; l >= 0; --l) {
        int M = BSZ << l;   // B * 2^l rows at this level
        tree_g1_kernel<<<M / 64, 256>>>(W_r1, b_r1, l);
        tree_g2_kernel<<<M / 64, 256>>>(W_r2, b_r2, l);
    }

    heads_kernel<<<BSZ, 128>>>(W_c1, b_c1, W_c2, b_c2, W_c3, b_c3,
                               W_d1, b_d1, W_d2, b_d2, W_d3, b_d3,
                               (float*)d_out);
}

// round 4
// speedup vs baseline: 1.9184x; 1.9144x over previous
#include <cuda_runtime.h>
#include <cuda_bf16.h>
#include <cstdint>
#include <math.h>

#define BSZ   2048
#define NROWS (BSZ * 63)   // 129024

// ---- scratch (device globals; no runtime allocation) ----
__device__ float g_X1[(size_t)NROWS * 256];   // [op_vec|c1|c2|bm] per node
__device__ float g_rep[(size_t)NROWS * 128];
__device__ float g_h[(size_t)65536 * 256];

// split-bf16 weights, transposed to [N][K] (K-major rows)
__device__ __nv_bfloat16 g_W1h[256 * 512],  g_W1l[256 * 512];
__device__ __nv_bfloat16 g_W2h[128 * 256],  g_W2l[128 * 256];
__device__ __nv_bfloat16 g_Wbmh[64 * 1024], g_Wbml[64 * 1024];
__device__ __nv_bfloat16 g_Woph[64 * 64],   g_Wopl[64 * 64];
__device__ __nv_bfloat16 g_Wprh[64 * 64],   g_Wprl[64 * 64];

// ---- helpers (base PTX only: ldmatrix / mma.sync / cp.async) ----
#define SWZ(o) ((o) ^ (((o) >> 3) & 0x70))

__device__ __forceinline__ uint32_t smem_u32(const void* p) {
    uint32_t a;
    asm("{ .reg .u64 t; cvta.to.shared.u64 t, %1; cvt.u32.u64 %0, t; }" : "=r"(a) : "l"(p));
    return a;
}
__device__ __forceinline__ void ldsm4(uint32_t* r, uint32_t addr) {
    asm volatile("ldmatrix.sync.aligned.m8n8.x4.shared.b16 {%0,%1,%2,%3}, [%4];"
                 : "=r"(r[0]), "=r"(r[1]), "=r"(r[2]), "=r"(r[3]) : "r"(addr));
}
__device__ __forceinline__ void mma16816(float* c, const uint32_t* a, const uint32_t* b) {
    asm volatile("mma.sync.aligned.m16n8k16.row.col.f32.bf16.bf16.f32 "
                 "{%0,%1,%2,%3}, {%4,%5,%6,%7}, {%8,%9}, {%0,%1,%2,%3};"
                 : "+f"(c[0]), "+f"(c[1]), "+f"(c[2]), "+f"(c[3])
                 : "r"(a[0]), "r"(a[1]), "r"(a[2]), "r"(a[3]), "r"(b[0]), "r"(b[1]));
}
__device__ __forceinline__ void cpa16(uint32_t dst, const void* src) {
    asm volatile("cp.async.cg.shared.global [%0], [%1], 16;" :: "r"(dst), "l"(src) : "memory");
}
__device__ __forceinline__ void split2(float x, float y, uint32_t& hi, uint32_t& lo) {
    float2 f = make_float2(x, y);
    __nv_bfloat162 h = __float22bfloat162_rn(f);
    float2 r = make_float2(x - __bfloat162float(h.x), y - __bfloat162float(h.y));
    __nv_bfloat162 l = __float22bfloat162_rn(r);
    hi = *reinterpret_cast<uint32_t*>(&h);
    lo = *reinterpret_cast<uint32_t*>(&l);
}
__device__ __forceinline__ void splitw(float v, __nv_bfloat16* ph, __nv_bfloat16* pl) {
    __nv_bfloat16 h = __float2bfloat16(v);
    *ph = h;
    *pl = __float2bfloat16(v - __bfloat162float(h));
}

// ---- weight prep: transpose + split fp32 -> bf16 hi/lo ----
__global__ void __launch_bounds__(256) prep_kernel(
    const float* __restrict__ W1, const float* __restrict__ W2,
    const float* __restrict__ Wbm, const float* __restrict__ Wop,
    const float* __restrict__ Wpr)
{
    int idx = blockIdx.x * 256 + threadIdx.x;
    if (idx < 131072) { int n = idx >> 9, k = idx & 511;
        splitw(W1[k * 256 + n], &g_W1h[idx], &g_W1l[idx]); return; }
    idx -= 131072;
    if (idx < 32768) { int n = idx >> 8, k = idx & 255;
        splitw(W2[k * 128 + n], &g_W2h[idx], &g_W2l[idx]); return; }
    idx -= 32768;
    if (idx < 65536) { int n = idx >> 10, k = idx & 1023;
        float v = (k < 1000) ? Wbm[k * 64 + n] : 0.f;
        splitw(v, &g_Wbmh[idx], &g_Wbml[idx]); return; }
    idx -= 65536;
    if (idx < 4096) { int n = idx >> 6, k = idx & 63;
        splitw(Wop[k * 64 + n], &g_Woph[idx], &g_Wopl[idx]); return; }
    idx -= 4096;
    if (idx < 4096) { int n = idx >> 6, k = idx & 63;
        splitw(Wpr[k * 64 + n], &g_Wprh[idx], &g_Wprl[idx]); }
}

// ============================================================
// mma.sync GEMM: M-tile 128, N-tile NT, K chunks of 64, 3-term bf16 split,
// cp.async double-buffered B, register-staged gathered A.
// ============================================================
enum { M_TREE1 = 0, M_TREE2 = 1, M_BM = 2, M_EMB = 3 };

template<int NT, int WN, int MODE, int KF>
__global__ void __launch_bounds__(128 * WN) gemm_ms(
    const float* __restrict__ Afp, const float* __restrict__ Afp2,
    const float* __restrict__ bias, const float* __restrict__ hc,
    int lvl, int xcol, int nch)
{
    constexpr int T      = 128 * WN;          // threads
    constexpr int BUF    = 32768 + NT * 256;  // Ah16K+Al16K + Bh+Bl
    constexpr int WARP_N = NT / WN;
    constexpr int NB8    = WARP_N / 8;
    constexpr int NT2    = WARP_N / 16;
    constexpr int TPR    = T / 128;           // threads per A-row
    constexpr int QPT    = 16 / TPR;          // float4 quads per thread

    extern __shared__ char smem[];
    const int tid  = threadIdx.x;
    const int m0   = blockIdx.x * 128;
    const int wid  = tid >> 5, lane = tid & 31;
    const int wm   = wid & 3,  wn   = wid >> 2;
    const uint32_t sb = smem_u32(smem);

    // ---- A gather setup (one row per thread group) ----
    const int arow  = tid / TPR;
    const int qbase = (tid % TPR) * QPT;
    const float *pX = nullptr, *pL = nullptr, *pR = nullptr;
    if (MODE == M_TREE1) {
        int lm = m0 + arow, nl = 1 << lvl;
        int lb = lm >> lvl, lj = (nl - 1) + (lm & (nl - 1));
        pX = g_X1 + (size_t)(lb * 63 + lj) * 256;
        int cl = 2 * lj + 1, cr = cl + 1;
        pL = (cl < 63) ? g_rep + (size_t)(lb * 63 + cl) * 128 : nullptr;
        pR = (cr < 63) ? g_rep + (size_t)(lb * 63 + cr) * 128 : nullptr;
    } else if (MODE == M_TREE2) pX = g_h + (size_t)(m0 + arow) * 256;
    else if (MODE == M_BM)      pX = Afp + (size_t)(m0 + arow) * 1000;

    const __nv_bfloat16 *Bh, *Bl;
    if      (MODE == M_TREE1) { Bh = g_W1h;  Bl = g_W1l;  }
    else if (MODE == M_TREE2) { Bh = g_W2h;  Bl = g_W2l;  }
    else if (MODE == M_BM)    { Bh = g_Wbmh; Bl = g_Wbml; }
    else                      { Bh = xcol ? g_Wprh : g_Woph; Bl = xcol ? g_Wprl : g_Wopl; }

    auto loadA = [&](int c, int buf) {
        char* sAh = smem + buf * BUF;
        char* sAl = sAh + 16384;
        #pragma unroll
        for (int i = 0; i < QPT; i++) {
            int q = qbase + i, kl = q * 4, kg = c * 64 + kl;
            float4 v = make_float4(0.f, 0.f, 0.f, 0.f);
            if (MODE == M_TREE1) {
                if (kg < 256)       v = *(const float4*)(pX + kg);
                else if (kg < 384) { if (pL) v = *(const float4*)(pL + kg - 256); }
                else               { if (pR) v = *(const float4*)(pR + kg - 384); }
            } else if (MODE == M_TREE2) {
                v = *(const float4*)(pX + kg);
            } else if (MODE == M_BM) {
                if (kg < 1000) v = *(const float4*)(pX + kg);
            } else {
                if (Afp2) v = (q < 8) ? *(const float4*)(Afp  + (size_t)(m0 + arow) * 32 + q * 4)
                                      : *(const float4*)(Afp2 + (size_t)(m0 + arow) * 32 + (q - 8) * 4);
                else      v = *(const float4*)(Afp + (size_t)(m0 + arow) * 64 + kl);
            }
            uint32_t h0, l0, h1, l1;
            split2(v.x, v.y, h0, l0);
            split2(v.z, v.w, h1, l1);
            uint32_t off = SWZ((uint32_t)(arow * 128 + kl * 2));
            *(uint2*)(sAh + off) = make_uint2(h0, h1);
            *(uint2*)(sAl + off) = make_uint2(l0, l1);
        }
    };
    auto loadB = [&](int c, int buf) {
        uint32_t dBh = sb + buf * BUF + 32768;
        uint32_t dBl = dBh + NT * 128;
        #pragma unroll
        for (int i = 0; i < NT * 16 / T; i++) {
            int idx  = tid + i * T;
            int half = idx >= NT * 8;
            int j    = half ? idx - NT * 8 : idx;
            int n = j >> 3, kq = j & 7;
            const __nv_bfloat16* src = (half ? Bl : Bh) + (size_t)n * KF + c * 64 + kq * 8;
            uint32_t dst = (half ? dBl : dBh) + SWZ((uint32_t)(n * 128 + kq * 16));
            cpa16(dst, src);
        }
    };

    float C[2][NB8][4];
    #pragma unroll
    for (int t = 0; t < 2; t++)
        #pragma unroll
        for (int j = 0; j < NB8; j++)
            #pragma unroll
            for (int q = 0; q < 4; q++) C[t][j][q] = 0.f;

    loadB(0, 0); loadA(0, 0);
    asm volatile("cp.async.commit_group;" ::: "memory");

    for (int c = 0; c < nch; c++) {
        const int buf = c & 1;
        if (c + 1 < nch) {
            loadB(c + 1, buf ^ 1); loadA(c + 1, buf ^ 1);
            asm volatile("cp.async.commit_group;" ::: "memory");
            asm volatile("cp.async.wait_group 1;" ::: "memory");
        } else {
            asm volatile("cp.async.wait_group 0;" ::: "memory");
        }
        __syncthreads();

        const uint32_t aH = sb + buf * BUF;
        const uint32_t aL = aH + 16384;
        const uint32_t bH = aH + 32768;
        const uint32_t bL = bH + NT * 128;

        #pragma unroll
        for (int k16 = 0; k16 < 4; k16++) {
            const int k0 = k16 * 16;
            uint32_t ah[2][4], al[2][4];
            const uint32_t abase = (uint32_t)((wm * 32 + (lane & 15)) * 128 + k0 * 2 + (lane >> 4) * 16);
            #pragma unroll
            for (int t = 0; t < 2; t++) {
                uint32_t o = SWZ(abase + t * 16 * 128);
                ldsm4(ah[t], aH + o);
                ldsm4(al[t], aL + o);
            }
            #pragma unroll
            for (int j = 0; j < NT2; j++) {
                const int brow = wn * WARP_N + j * 16 + ((lane >> 4) << 3) + (lane & 7);
                const uint32_t bo = SWZ((uint32_t)(brow * 128 + (k0 + ((lane >> 3) & 1) * 8) * 2));
                uint32_t bh[4], blr[4];
                ldsm4(bh,  bH + bo);
                ldsm4(blr, bL + bo);
                #pragma unroll
                for (int t = 0; t < 2; t++) {
                    mma16816(C[t][2 * j],     ah[t], bh);
                    mma16816(C[t][2 * j + 1], ah[t], bh + 2);
                    mma16816(C[t][2 * j],     al[t], bh);
                    mma16816(C[t][2 * j + 1], al[t], bh + 2);
                    mma16816(C[t][2 * j],     ah[t], blr);
                    mma16816(C[t][2 * j + 1], ah[t], blr + 2);
                }
            }
        }
        __syncthreads();
    }

    // ---- epilogue ----
    #pragma unroll
    for (int t = 0; t < 2; t++) {
        const int r1 = m0 + wm * 32 + t * 16 + (lane >> 2);
        const int r2 = r1 + 8;
        float *d1, *d2;
        float hv1 = 1.f, hv2 = 1.f;
        if (MODE == M_TREE1) {
            d1 = g_h + (size_t)r1 * 256; d2 = g_h + (size_t)r2 * 256;
        } else if (MODE == M_TREE2) {
            int nl = 1 << lvl;
            int b1 = r1 >> lvl, j1 = (nl - 1) + (r1 & (nl - 1));
            int b2 = r2 >> lvl, j2 = (nl - 1) + (r2 & (nl - 1));
            d1 = g_rep + (size_t)(b1 * 63 + j1) * 128;
            d2 = g_rep + (size_t)(b2 * 63 + j2) * 128;
        } else if (MODE == M_BM) {
            d1 = g_X1 + (size_t)r1 * 256 + 192; d2 = g_X1 + (size_t)r2 * 256 + 192;
            hv1 = hc[r1]; hv2 = hc[r2];
        } else {
            d1 = g_X1 + (size_t)r1 * 256 + xcol; d2 = g_X1 + (size_t)r2 * 256 + xcol;
        }
        #pragma unroll
        for (int j8 = 0; j8 < NB8; j8++) {
            const int n = wn * WARP_N + j8 * 8 + (lane & 3) * 2;
            float2 bb = *(const float2*)(bias + n);
            float v0 = C[t][j8][0] + bb.x, v1 = C[t][j8][1] + bb.y;
            float v2 = C[t][j8][2] + bb.x, v3 = C[t][j8][3] + bb.y;
            if (MODE == M_TREE1 || MODE == M_TREE2) {
                v0 = fmaxf(v0, 0.f); v1 = fmaxf(v1, 0.f);
                v2 = fmaxf(v2, 0.f); v3 = fmaxf(v3, 0.f);
            } else if (MODE == M_BM) {
                v0 *= hv1; v1 *= hv1; v2 *= hv2; v3 *= hv2;
            }
            *(float2*)(d1 + n) = make_float2(v0, v1);
            *(float2*)(d2 + n) = make_float2(v2, v3);
        }
    }
}

// ---- heads (tiny fp32) ----
__global__ void __launch_bounds__(128) heads_kernel(
    const float* __restrict__ Wc1, const float* __restrict__ bc1,
    const float* __restrict__ Wc2, const float* __restrict__ bc2,
    const float* __restrict__ Wc3, const float* __restrict__ bc3,
    const float* __restrict__ Wd1, const float* __restrict__ bd1,
    const float* __restrict__ Wd2, const float* __restrict__ bd2,
    const float* __restrict__ Wd3, const float* __restrict__ bd3,
    float* __restrict__ out)
{
    __shared__ float sroot[128];
    __shared__ float sh1[128];
    __shared__ float sprod[128];
    int b = blockIdx.x, t = threadIdx.x;
    sroot[t] = g_rep[(size_t)(b * 63) * 128 + t];
    __syncthreads();

    int head = t >> 6, c = t & 63;
    const float* W1 = head ? Wd1 : Wc1; const float* B1 = head ? bd1 : bc1;
    const float* W2 = head ? Wd2 : Wc2; const float* B2 = head ? bd2 : bc2;
    const float* W3 = head ? Wd3 : Wc3; const float* B3 = head ? bd3 : bc3;

    float h = B1[c];
    #pragma unroll 8
    for (int k = 0; k < 128; k++) h += sroot[k] * W1[k * 64 + c];
    sh1[t] = fmaxf(h, 0.f);
    __syncthreads();

    float h2 = B2[c];
    #pragma unroll 8
    for (int k = 0; k < 64; k++) h2 += sh1[head * 64 + k] * W2[k * 64 + c];
    h2 = fmaxf(h2, 0.f);
    sprod[t] = h2 * W3[c];
    __syncthreads();

    if (c == 0) {
        float s = B3[0];
        #pragma unroll 8
        for (int k = 0; k < 64; k++) s += sprod[head * 64 + k];
        out[head * BSZ + b] = 1.f / (1.f + expf(-s));
    }
}

// ---- launch ----
#define SM_T1  (2 * (32768 + 256 * 256))  // 196608
#define SM_T2  (2 * (32768 + 128 * 256))  // 131072
#define SM_BM  (2 * (32768 +  64 * 256))  //  98304
#define SM_EMB (2 * (32768 +  64 * 256))  //  98304

extern "C" void kernel_launch(void* const* d_in, const int* in_sizes, int n_in,
                              void* d_out, int out_size)
{
    const float* op      = (const float*)d_in[0];
    const float* extra   = (const float*)d_in[1];
    const float* cond1   = (const float*)d_in[2];
    const float* cond2   = (const float*)d_in[3];
    const float* bitmap  = (const float*)d_in[4];
    const float* hascond = (const float*)d_in[5];
    const float* W_op = (const float*)d_in[6];   const float* b_op = (const float*)d_in[7];
    const float* W_pr = (const float*)d_in[8];   const float* b_pr = (const float*)d_in[9];
    const float* W_bm = (const float*)d_in[10];  const float* b_bm = (const float*)d_in[11];
    const float* W_r1 = (const float*)d_in[12];  const float* b_r1 = (const float*)d_in[13];
    const float* W_r2 = (const float*)d_in[14];  const float* b_r2 = (const float*)d_in[15];
    const float* W_c1 = (const float*)d_in[16];  const float* b_c1 = (const float*)d_in[17];
    const float* W_c2 = (const float*)d_in[18];  const float* b_c2 = (const float*)d_in[19];
    const float* W_c3 = (const float*)d_in[20];  const float* b_c3 = (const float*)d_in[21];
    const float* W_d1 = (const float*)d_in[22];  const float* b_d1 = (const float*)d_in[23];
    const float* W_d2 = (const float*)d_in[24];  const float* b_d2 = (const float*)d_in[25];
    const float* W_d3 = (const float*)d_in[26];  const float* b_d3 = (const float*)d_in[27];

    cudaFuncSetAttribute(gemm_ms<256, 4, M_TREE1, 512>,  cudaFuncAttributeMaxDynamicSharedMemorySize, SM_T1);
    cudaFuncSetAttribute(gemm_ms<128, 2, M_TREE2, 256>,  cudaFuncAttributeMaxDynamicSharedMemorySize, SM_T2);
    cudaFuncSetAttribute(gemm_ms< 64, 2, M_BM,    1024>, cudaFuncAttributeMaxDynamicSharedMemorySize, SM_BM);
    cudaFuncSetAttribute(gemm_ms< 64, 2, M_EMB,   64>,   cudaFuncAttributeMaxDynamicSharedMemorySize, SM_EMB);

    prep_kernel<<<928, 256>>>(W_r1, W_r2, W_bm, W_op, W_pr);

    // embeddings (X1 cols 0..191) + bitmap embed (cols 192..255)
    gemm_ms<64, 2, M_EMB, 64><<<NROWS / 128, 256, SM_EMB>>>(op,    extra,   b_op, nullptr, 0, 0,   1);
    gemm_ms<64, 2, M_EMB, 64><<<NROWS / 128, 256, SM_EMB>>>(cond1, nullptr, b_pr, nullptr, 0, 64,  1);
    gemm_ms<64, 2, M_EMB, 64><<<NROWS / 128, 256, SM_EMB>>>(cond2, nullptr, b_pr, nullptr, 0, 128, 1);
    gemm_ms<64, 2, M_BM, 1024><<<NROWS / 128, 256, SM_BM>>>(bitmap, nullptr, b_bm, hascond, 0, 0, 16);

    // tree levels, leaves -> root (leaf level: children are zero => K_eff=256)
    for (int l = 5; l >= 0; --l) {
        int blocks = (BSZ << l) / 128;
        int nch1 = (l == 5) ? 4 : 8;
        gemm_ms<256, 4, M_TREE1, 512><<<blocks, 512, SM_T1>>>(nullptr, nullptr, b_r1, nullptr, l, 0, nch1);
        gemm_ms<128, 2, M_TREE2, 256><<<blocks, 256, SM_T2>>>(nullptr, nullptr, b_r2, nullptr, l, 0, 4);
    }

    heads_kernel<<<BSZ, 128>>>(W_c1, b_c1, W_c2, b_c2, W_c3, b_c3,
                               W_d1, b_d1, W_d2, b_d2, W_d3, b_d3,
                               (float*)d_out);
}

// round 5
// speedup vs baseline: 2.4708x; 1.2879x over previous
#include <cuda_runtime.h>
#include <cuda_bf16.h>
#include <cstdint>
#include <math.h>

#define BSZ   2048
#define NROWS (BSZ * 63)   // 129024

// ---- scratch (device globals; pre-split bf16 hi/lo activations) ----
__device__ __nv_bfloat16 g_X1h[(size_t)NROWS * 256], g_X1l[(size_t)NROWS * 256];
__device__ __nv_bfloat16 g_reph[(size_t)NROWS * 128], g_repl[(size_t)NROWS * 128];

// split-bf16 weights, transposed to [N][K]
__device__ __nv_bfloat16 g_W1h[256 * 512],  g_W1l[256 * 512];
__device__ __nv_bfloat16 g_W2h[128 * 256],  g_W2l[128 * 256];
__device__ __nv_bfloat16 g_Wbmh[64 * 1024], g_Wbml[64 * 1024];
__device__ __nv_bfloat16 g_Woph[64 * 64],   g_Wopl[64 * 64];
__device__ __nv_bfloat16 g_Wprh[64 * 64],   g_Wprl[64 * 64];

// ---- helpers ----
#define SWZ(o) ((o) ^ (((o) >> 3) & 0x70))

__device__ __forceinline__ uint32_t smem_u32(const void* p) {
    uint32_t a;
    asm("{ .reg .u64 t; cvta.to.shared.u64 t, %1; cvt.u32.u64 %0, t; }" : "=r"(a) : "l"(p));
    return a;
}
__device__ __forceinline__ void ldsm4(uint32_t* r, uint32_t addr) {
    asm volatile("ldmatrix.sync.aligned.m8n8.x4.shared.b16 {%0,%1,%2,%3}, [%4];"
                 : "=r"(r[0]), "=r"(r[1]), "=r"(r[2]), "=r"(r[3]) : "r"(addr));
}
__device__ __forceinline__ void mma16816(float* c, const uint32_t* a, const uint32_t* b) {
    asm volatile("mma.sync.aligned.m16n8k16.row.col.f32.bf16.bf16.f32 "
                 "{%0,%1,%2,%3}, {%4,%5,%6,%7}, {%8,%9}, {%0,%1,%2,%3};"
                 : "+f"(c[0]), "+f"(c[1]), "+f"(c[2]), "+f"(c[3])
                 : "r"(a[0]), "r"(a[1]), "r"(a[2]), "r"(a[3]), "r"(b[0]), "r"(b[1]));
}
__device__ __forceinline__ void cpa16(uint32_t dst, const void* src) {
    asm volatile("cp.async.cg.shared.global [%0], [%1], 16;" :: "r"(dst), "l"(src) : "memory");
}
__device__ __forceinline__ void cpcommit() { asm volatile("cp.async.commit_group;" ::: "memory"); }
__device__ __forceinline__ void cpwait0()  { asm volatile("cp.async.wait_group 0;" ::: "memory"); }
__device__ __forceinline__ void cpwait1()  { asm volatile("cp.async.wait_group 1;" ::: "memory"); }
__device__ __forceinline__ void cpwait2()  { asm volatile("cp.async.wait_group 2;" ::: "memory"); }

__device__ __forceinline__ void split2(float x, float y, uint32_t& hi, uint32_t& lo) {
    float2 f = make_float2(x, y);
    __nv_bfloat162 h = __float22bfloat162_rn(f);
    float2 r = make_float2(x - __bfloat162float(h.x), y - __bfloat162float(h.y));
    __nv_bfloat162 l = __float22bfloat162_rn(r);
    hi = *reinterpret_cast<uint32_t*>(&h);
    lo = *reinterpret_cast<uint32_t*>(&l);
}
__device__ __forceinline__ void splitw(float v, __nv_bfloat16* ph, __nv_bfloat16* pl) {
    __nv_bfloat16 h = __float2bfloat16(v);
    *ph = h;
    *pl = __float2bfloat16(v - __bfloat162float(h));
}

// ---- weight prep ----
__global__ void __launch_bounds__(256) prep_kernel(
    const float* __restrict__ W1, const float* __restrict__ W2,
    const float* __restrict__ Wbm, const float* __restrict__ Wop,
    const float* __restrict__ Wpr)
{
    int idx = blockIdx.x * 256 + threadIdx.x;
    if (idx < 131072) { int n = idx >> 9, k = idx & 511;
        splitw(W1[k * 256 + n], &g_W1h[idx], &g_W1l[idx]); return; }
    idx -= 131072;
    if (idx < 32768) { int n = idx >> 8, k = idx & 255;
        splitw(W2[k * 128 + n], &g_W2h[idx], &g_W2l[idx]); return; }
    idx -= 32768;
    if (idx < 65536) { int n = idx >> 10, k = idx & 1023;
        float v = (k < 1000) ? Wbm[k * 64 + n] : 0.f;
        splitw(v, &g_Wbmh[idx], &g_Wbml[idx]); return; }
    idx -= 65536;
    if (idx < 4096) { int n = idx >> 6, k = idx & 63;
        splitw(Wop[k * 64 + n], &g_Woph[idx], &g_Wopl[idx]); return; }
    idx -= 4096;
    if (idx < 4096) { int n = idx >> 6, k = idx & 63;
        splitw(Wpr[k * 64 + n], &g_Wprh[idx], &g_Wprl[idx]); }
}

// ============================================================
// Fused embeds: X1[:,0:192] = three 64x64 GEMMs in one launch
// 256 threads, warp grid 4(m) x 2(n), warp tile 32x32
// ============================================================
__global__ void __launch_bounds__(256) embed3_kernel(
    const float* __restrict__ op, const float* __restrict__ extra,
    const float* __restrict__ c1, const float* __restrict__ c2,
    const float* __restrict__ bop, const float* __restrict__ bpr)
{
    extern __shared__ char smem[];
    const uint32_t sb = smem_u32(smem);
    const int tid = threadIdx.x, m0 = blockIdx.x * 128;
    const int wid = tid >> 5, lane = tid & 31;
    const int wm = wid & 3, wn = wid >> 2;

    for (int s = 0; s < 3; s++) {
        const float* Asrc = (s == 0) ? op : (s == 1 ? c1 : c2);
        const __nv_bfloat16* Wh = (s == 0) ? g_Woph : g_Wprh;
        const __nv_bfloat16* Wl = (s == 0) ? g_Wopl : g_Wprl;
        // A: 128 rows x 64 k fp32 -> split -> SMEM
        #pragma unroll
        for (int i = 0; i < 8; i++) {
            int idx = i * 256 + tid;
            int row = idx >> 4, q4 = idx & 15, kl = q4 * 4;
            float4 v;
            if (s == 0) v = (kl < 32) ? *(const float4*)(op    + (size_t)(m0 + row) * 32 + kl)
                                      : *(const float4*)(extra + (size_t)(m0 + row) * 32 + kl - 32);
            else        v = *(const float4*)(Asrc + (size_t)(m0 + row) * 64 + kl);
            uint32_t h0, l0, h1, l1;
            split2(v.x, v.y, h0, l0); split2(v.z, v.w, h1, l1);
            uint32_t o = SWZ((uint32_t)(row * 128 + q4 * 8));
            *(uint2*)(smem + o)         = make_uint2(h0, h1);
            *(uint2*)(smem + 16384 + o) = make_uint2(l0, l1);
        }
        // B: cp.async
        #pragma unroll
        for (int i = 0; i < 4; i++) {
            int idx = i * 256 + tid;
            int half = idx >> 9, j = idx & 511, n = j >> 3, q = j & 7;
            cpa16(sb + 32768 + half * 8192 + SWZ((uint32_t)(n * 128 + q * 16)),
                  (half ? Wl : Wh) + (size_t)n * 64 + q * 8);
        }
        cpcommit(); cpwait0();
        __syncthreads();

        float C[2][4][4] = {};
        #pragma unroll
        for (int k16 = 0; k16 < 4; k16++) {
            const int k0 = k16 * 16;
            uint32_t ah[2][4], al[2][4];
            const uint32_t abase = (uint32_t)((wm * 32 + (lane & 15)) * 128 + k0 * 2 + (lane >> 4) * 16);
            #pragma unroll
            for (int t = 0; t < 2; t++) {
                uint32_t o = SWZ(abase + t * 2048);
                ldsm4(ah[t], sb + o);
                ldsm4(al[t], sb + 16384 + o);
            }
            #pragma unroll
            for (int j = 0; j < 2; j++) {
                const int brow = wn * 32 + j * 16 + ((lane >> 4) << 3) + (lane & 7);
                const uint32_t bo = SWZ((uint32_t)(brow * 128 + (k0 + ((lane >> 3) & 1) * 8) * 2));
                uint32_t bh[4], bl[4];
                ldsm4(bh, sb + 32768 + bo);
                ldsm4(bl, sb + 40960 + bo);
                #pragma unroll
                for (int t = 0; t < 2; t++) {
                    mma16816(C[t][2 * j],     ah[t], bh);
                    mma16816(C[t][2 * j + 1], ah[t], bh + 2);
                    mma16816(C[t][2 * j],     al[t], bh);
                    mma16816(C[t][2 * j + 1], al[t], bh + 2);
                    mma16816(C[t][2 * j],     ah[t], bl);
                    mma16816(C[t][2 * j + 1], ah[t], bl + 2);
                }
            }
        }
        // epilogue: split-store to X1h/X1l at cols s*64..
        const float* bias = (s == 0) ? bop : bpr;
        #pragma unroll
        for (int t = 0; t < 2; t++) {
            const int r1 = m0 + wm * 32 + t * 16 + (lane >> 2);
            #pragma unroll
            for (int j8 = 0; j8 < 4; j8++) {
                const int n = wn * 32 + j8 * 8 + (lane & 3) * 2;
                float2 bb = *(const float2*)(bias + n);
                float v0 = C[t][j8][0] + bb.x, v1 = C[t][j8][1] + bb.y;
                float v2 = C[t][j8][2] + bb.x, v3 = C[t][j8][3] + bb.y;
                uint32_t h01, l01, h23, l23;
                split2(v0, v1, h01, l01); split2(v2, v3, h23, l23);
                size_t o1 = (size_t)r1 * 256 + s * 64 + n;
                size_t o2 = o1 + 8 * 256;
                *(uint32_t*)(g_X1h + o1) = h01; *(uint32_t*)(g_X1l + o1) = l01;
                *(uint32_t*)(g_X1h + o2) = h23; *(uint32_t*)(g_X1l + o2) = l23;
            }
        }
        __syncthreads();
    }
}

// ============================================================
// Bitmap embed: X1[:,192:256] = (bitmap @ W_bm + b_bm) * has_cond
// 3-deep cp.async fp32 staging + in-SMEM convert. 256 threads.
// SMEM: S fp32 3x32K @0 | A bf16 2x32K @98304 | B 3x16K @163840
// ============================================================
__global__ void __launch_bounds__(256) bm_kernel(
    const float* __restrict__ bm, const float* __restrict__ hc,
    const float* __restrict__ bbm)
{
    extern __shared__ char smem[];
    const uint32_t sb = smem_u32(smem);
    const int tid = threadIdx.x, m0 = blockIdx.x * 128;
    const int wid = tid >> 5, lane = tid & 31;
    const int wm = wid & 3, wn = wid >> 2;

    auto loadStage = [&](int c, int s) {
        #pragma unroll
        for (int i = 0; i < 8; i++) {
            int idx = i * 256 + tid;
            int row = idx >> 4, q4 = idx & 15;
            int kg4 = c * 16 + q4;
            uint32_t dst = sb + s * 32768 + row * 256 + q4 * 16;
            if (kg4 < 250) cpa16(dst, bm + (size_t)(m0 + row) * 1000 + kg4 * 4);
            else *(uint4*)(smem + s * 32768 + row * 256 + q4 * 16) = make_uint4(0, 0, 0, 0);
        }
        #pragma unroll
        for (int i = 0; i < 4; i++) {
            int idx = i * 256 + tid;
            int half = idx >> 9, j = idx & 511, n = j >> 3, q = j & 7;
            cpa16(sb + 163840 + s * 16384 + half * 8192 + SWZ((uint32_t)(n * 128 + q * 16)),
                  (half ? g_Wbml : g_Wbmh) + (size_t)n * 1024 + c * 64 + q * 8);
        }
    };

    float C[2][4][4] = {};
    loadStage(0, 0); cpcommit();
    loadStage(1, 1); cpcommit();
    loadStage(2, 2); cpcommit();

    for (int c = 0; c < 16; c++) {
        const int s = c % 3, buf = c & 1;
        cpwait2();
        __syncthreads();
        // convert fp32 stage -> bf16 hi/lo A buffer
        #pragma unroll
        for (int i = 0; i < 8; i++) {
            int idx = i * 256 + tid;
            int row = idx >> 4, q4 = idx & 15;
            float4 v = *(const float4*)(smem + s * 32768 + row * 256 + q4 * 16);
            uint32_t h0, l0, h1, l1;
            split2(v.x, v.y, h0, l0); split2(v.z, v.w, h1, l1);
            uint32_t o = SWZ((uint32_t)(row * 128 + q4 * 8));
            *(uint2*)(smem + 98304 + buf * 32768 + o)         = make_uint2(h0, h1);
            *(uint2*)(smem + 98304 + buf * 32768 + 16384 + o) = make_uint2(l0, l1);
        }
        __syncthreads();

        const uint32_t aH = sb + 98304 + buf * 32768, aL = aH + 16384;
        const uint32_t bH = sb + 163840 + s * 16384,  bL = bH + 8192;
        #pragma unroll
        for (int k16 = 0; k16 < 4; k16++) {
            const int k0 = k16 * 16;
            uint32_t ah[2][4], al[2][4];
            const uint32_t abase = (uint32_t)((wm * 32 + (lane & 15)) * 128 + k0 * 2 + (lane >> 4) * 16);
            #pragma unroll
            for (int t = 0; t < 2; t++) {
                uint32_t o = SWZ(abase + t * 2048);
                ldsm4(ah[t], aH + o);
                ldsm4(al[t], aL + o);
            }
            #pragma unroll
            for (int j = 0; j < 2; j++) {
                const int brow = wn * 32 + j * 16 + ((lane >> 4) << 3) + (lane & 7);
                const uint32_t bo = SWZ((uint32_t)(brow * 128 + (k0 + ((lane >> 3) & 1) * 8) * 2));
                uint32_t bh[4], bl[4];
                ldsm4(bh, bH + bo);
                ldsm4(bl, bL + bo);
                #pragma unroll
                for (int t = 0; t < 2; t++) {
                    mma16816(C[t][2 * j],     ah[t], bh);
                    mma16816(C[t][2 * j + 1], ah[t], bh + 2);
                    mma16816(C[t][2 * j],     al[t], bh);
                    mma16816(C[t][2 * j + 1], al[t], bh + 2);
                    mma16816(C[t][2 * j],     ah[t], bl);
                    mma16816(C[t][2 * j + 1], ah[t], bl + 2);
                }
            }
        }
        __syncthreads();
        if (c + 3 < 16) loadStage(c + 3, s);
        cpcommit();
    }

    // epilogue -> X1 cols 192..255 (split bf16)
    #pragma unroll
    for (int t = 0; t < 2; t++) {
        const int r1 = m0 + wm * 32 + t * 16 + (lane >> 2);
        const int r2 = r1 + 8;
        float hv1 = hc[r1], hv2 = hc[r2];
        #pragma unroll
        for (int j8 = 0; j8 < 4; j8++) {
            const int n = wn * 32 + j8 * 8 + (lane & 3) * 2;
            float2 bb = *(const float2*)(bbm + n);
            float v0 = (C[t][j8][0] + bb.x) * hv1, v1 = (C[t][j8][1] + bb.y) * hv1;
            float v2 = (C[t][j8][2] + bb.x) * hv2, v3 = (C[t][j8][3] + bb.y) * hv2;
            uint32_t h01, l01, h23, l23;
            split2(v0, v1, h01, l01); split2(v2, v3, h23, l23);
            size_t o1 = (size_t)r1 * 256 + 192 + n;
            size_t o2 = (size_t)r2 * 256 + 192 + n;
            *(uint32_t*)(g_X1h + o1) = h01; *(uint32_t*)(g_X1l + o1) = l01;
            *(uint32_t*)(g_X1h + o2) = h23; *(uint32_t*)(g_X1l + o2) = l23;
        }
    }
}

// ============================================================
// Fused tree level: h = relu([X|L|R]@W1+b1); rep = relu(h@W2+b2)
// 512 threads (16 warps: 4m x 4n). Phase1: M128 N256 K512 (K256 at leaf).
// Phase2: M128 N128 K256 from SMEM H.
// SMEM: A bufs 2x32K @0 | B bufs 2x64K @65536 (reused: Hh 4x16K @65536, Hl @131072)
// ============================================================
__global__ void __launch_bounds__(512, 1) tree_fused_kernel(
    const float* __restrict__ b1, const float* __restrict__ b2, int lvl, int nch)
{
    extern __shared__ char smem[];
    const uint32_t sb = smem_u32(smem);
    const int tid = threadIdx.x, m0 = blockIdx.x * 128;
    const int wid = tid >> 5, lane = tid & 31;
    const int wm = wid & 3, wn = wid >> 2;
    const int nl = 1 << lvl;

    auto loadA1 = [&](int c, int buf) {
        const uint32_t base = sb + buf * 32768;
        #pragma unroll
        for (int i = 0; i < 4; i++) {
            int idx = i * 512 + tid;
            int half = idx >> 10, j = idx & 1023, row = j >> 3, q = j & 7;
            int lm = m0 + row, lb = lm >> lvl, lj = (nl - 1) + (lm & (nl - 1));
            const __nv_bfloat16* src;
            if (c < 4)      src = (half ? g_X1l : g_X1h) + (size_t)(lb * 63 + lj) * 256 + c * 64 + q * 8;
            else if (c < 6) src = (half ? g_repl : g_reph) + (size_t)(lb * 63 + 2 * lj + 1) * 128 + (c - 4) * 64 + q * 8;
            else            src = (half ? g_repl : g_reph) + (size_t)(lb * 63 + 2 * lj + 2) * 128 + (c - 6) * 64 + q * 8;
            cpa16(base + half * 16384 + SWZ((uint32_t)(row * 128 + q * 16)), src);
        }
    };
    auto loadB1 = [&](int c, int buf) {
        const uint32_t base = sb + 65536 + buf * 65536;
        #pragma unroll
        for (int i = 0; i < 8; i++) {
            int idx = i * 512 + tid;
            int half = idx >> 11, j = idx & 2047, n = j >> 3, q = j & 7;
            cpa16(base + half * 32768 + SWZ((uint32_t)(n * 128 + q * 16)),
                  (half ? g_W1l : g_W1h) + (size_t)n * 512 + c * 64 + q * 8);
        }
    };
    auto loadB2 = [&](int c, int buf) {
        const uint32_t base = sb + buf * 32768;
        #pragma unroll
        for (int i = 0; i < 4; i++) {
            int idx = i * 512 + tid;
            int half = idx >> 10, j = idx & 1023, n = j >> 3, q = j & 7;
            cpa16(base + half * 16384 + SWZ((uint32_t)(n * 128 + q * 16)),
                  (half ? g_W2l : g_W2h) + (size_t)n * 256 + c * 64 + q * 8);
        }
    };

    // ---------------- phase 1 ----------------
    float C[2][8][4] = {};
    loadB1(0, 0); loadA1(0, 0); cpcommit();
    for (int c = 0; c < nch; c++) {
        const int buf = c & 1;
        if (c + 1 < nch) {
            loadB1(c + 1, buf ^ 1); loadA1(c + 1, buf ^ 1);
            cpcommit(); cpwait1();
        } else cpwait0();
        __syncthreads();
        const uint32_t aH = sb + buf * 32768, aL = aH + 16384;
        const uint32_t bH = sb + 65536 + buf * 65536, bL = bH + 32768;
        #pragma unroll
        for (int k16 = 0; k16 < 4; k16++) {
            const int k0 = k16 * 16;
            uint32_t ah[2][4], al[2][4];
            const uint32_t abase = (uint32_t)((wm * 32 + (lane & 15)) * 128 + k0 * 2 + (lane >> 4) * 16);
            #pragma unroll
            for (int t = 0; t < 2; t++) {
                uint32_t o = SWZ(abase + t * 2048);
                ldsm4(ah[t], aH + o);
                ldsm4(al[t], aL + o);
            }
            #pragma unroll
            for (int j = 0; j < 4; j++) {
                const int brow = wn * 64 + j * 16 + ((lane >> 4) << 3) + (lane & 7);
                const uint32_t bo = SWZ((uint32_t)(brow * 128 + (k0 + ((lane >> 3) & 1) * 8) * 2));
                uint32_t bh[4], bl[4];
                ldsm4(bh, bH + bo);
                ldsm4(bl, bL + bo);
                #pragma unroll
                for (int t = 0; t < 2; t++) {
                    mma16816(C[t][2 * j],     ah[t], bh);
                    mma16816(C[t][2 * j + 1], ah[t], bh + 2);
                    mma16816(C[t][2 * j],     al[t], bh);
                    mma16816(C[t][2 * j + 1], al[t], bh + 2);
                    mma16816(C[t][2 * j],     ah[t], bl);
                    mma16816(C[t][2 * j + 1], ah[t], bl + 2);
                }
            }
        }
        __syncthreads();
    }

    // ---------------- phase 1 -> H (SMEM), start W2 loads ----------------
    loadB2(0, 0); cpcommit();
    loadB2(1, 1); cpcommit();
    #pragma unroll
    for (int t = 0; t < 2; t++) {
        const int rloc = wm * 32 + t * 16 + (lane >> 2);
        #pragma unroll
        for (int j8 = 0; j8 < 8; j8++) {
            const int n0 = wn * 64 + j8 * 8 + (lane & 3) * 2;
            float2 bb = *(const float2*)(b1 + n0);
            float v0 = fmaxf(C[t][j8][0] + bb.x, 0.f), v1 = fmaxf(C[t][j8][1] + bb.y, 0.f);
            float v2 = fmaxf(C[t][j8][2] + bb.x, 0.f), v3 = fmaxf(C[t][j8][3] + bb.y, 0.f);
            uint32_t h01, l01, h23, l23;
            split2(v0, v1, h01, l01); split2(v2, v3, h23, l23);
            const uint32_t cbase = 65536 + (n0 >> 6) * 16384;
            const uint32_t o1 = SWZ((uint32_t)(rloc * 128 + (n0 & 63) * 2));
            const uint32_t o2 = SWZ((uint32_t)((rloc + 8) * 128 + (n0 & 63) * 2));
            *(uint32_t*)(smem + cbase + o1)         = h01;
            *(uint32_t*)(smem + cbase + 65536 + o1) = l01;
            *(uint32_t*)(smem + cbase + o2)         = h23;
            *(uint32_t*)(smem + cbase + 65536 + o2) = l23;
        }
    }
    __syncthreads();

    // ---------------- phase 2: rep = relu(H @ W2 + b2) ----------------
    float C2[2][4][4] = {};
    for (int c2 = 0; c2 < 4; c2++) {
        if (c2 < 3) cpwait1(); else cpwait0();
        __syncthreads();
        const uint32_t aH = sb + 65536 + c2 * 16384, aL = aH + 65536;
        const uint32_t bH = sb + (c2 & 1) * 32768,   bL = bH + 16384;
        #pragma unroll
        for (int k16 = 0; k16 < 4; k16++) {
            const int k0 = k16 * 16;
            uint32_t ah[2][4], al[2][4];
            const uint32_t abase = (uint32_t)((wm * 32 + (lane & 15)) * 128 + k0 * 2 + (lane >> 4) * 16);
            #pragma unroll
            for (int t = 0; t < 2; t++) {
                uint32_t o = SWZ(abase + t * 2048);
                ldsm4(ah[t], aH + o);
                ldsm4(al[t], aL + o);
            }
            #pragma unroll
            for (int j = 0; j < 2; j++) {
                const int brow = wn * 32 + j * 16 + ((lane >> 4) << 3) + (lane & 7);
                const uint32_t bo = SWZ((uint32_t)(brow * 128 + (k0 + ((lane >> 3) & 1) * 8) * 2));
                uint32_t bh[4], bl[4];
                ldsm4(bh, bH + bo);
                ldsm4(bl, bL + bo);
                #pragma unroll
                for (int t = 0; t < 2; t++) {
                    mma16816(C2[t][2 * j],     ah[t], bh);
                    mma16816(C2[t][2 * j + 1], ah[t], bh + 2);
                    mma16816(C2[t][2 * j],     al[t], bh);
                    mma16816(C2[t][2 * j + 1], al[t], bh + 2);
                    mma16816(C2[t][2 * j],     ah[t], bl);
                    mma16816(C2[t][2 * j + 1], ah[t], bl + 2);
                }
            }
        }
        __syncthreads();
        if (c2 + 2 < 4) { loadB2(c2 + 2, c2 & 1); }
        cpcommit();
    }

    // epilogue: scatter rep (split bf16) by node index
    #pragma unroll
    for (int t = 0; t < 2; t++) {
        const int r1 = m0 + wm * 32 + t * 16 + (lane >> 2);
        const int r2 = r1 + 8;
        const int b1i = r1 >> lvl, j1 = (nl - 1) + (r1 & (nl - 1));
        const int b2i = r2 >> lvl, j2 = (nl - 1) + (r2 & (nl - 1));
        const size_t n1 = (size_t)(b1i * 63 + j1) * 128;
        const size_t n2 = (size_t)(b2i * 63 + j2) * 128;
        #pragma unroll
        for (int j8 = 0; j8 < 4; j8++) {
            const int n = wn * 32 + j8 * 8 + (lane & 3) * 2;
            float2 bb = *(const float2*)(b2 + n);
            float v0 = fmaxf(C2[t][j8][0] + bb.x, 0.f), v1 = fmaxf(C2[t][j8][1] + bb.y, 0.f);
            float v2 = fmaxf(C2[t][j8][2] + bb.x, 0.f), v3 = fmaxf(C2[t][j8][3] + bb.y, 0.f);
            uint32_t h01, l01, h23, l23;
            split2(v0, v1, h01, l01); split2(v2, v3, h23, l23);
            *(uint32_t*)(g_reph + n1 + n) = h01; *(uint32_t*)(g_repl + n1 + n) = l01;
            *(uint32_t*)(g_reph + n2 + n) = h23; *(uint32_t*)(g_repl + n2 + n) = l23;
        }
    }
}

// ---- heads ----
__global__ void __launch_bounds__(128) heads_kernel(
    const float* __restrict__ Wc1, const float* __restrict__ bc1,
    const float* __restrict__ Wc2, const float* __restrict__ bc2,
    const float* __restrict__ Wc3, const float* __restrict__ bc3,
    const float* __restrict__ Wd1, const float* __restrict__ bd1,
    const float* __restrict__ Wd2, const float* __restrict__ bd2,
    const float* __restrict__ Wd3, const float* __restrict__ bd3,
    float* __restrict__ out)
{
    __shared__ float sroot[128];
    __shared__ float sh1[128];
    __shared__ float sprod[128];
    int b = blockIdx.x, t = threadIdx.x;
    size_t ro = (size_t)(b * 63) * 128 + t;
    sroot[t] = __bfloat162float(g_reph[ro]) + __bfloat162float(g_repl[ro]);
    __syncthreads();

    int head = t >> 6, c = t & 63;
    const float* W1 = head ? Wd1 : Wc1; const float* B1 = head ? bd1 : bc1;
    const float* W2 = head ? Wd2 : Wc2; const float* B2 = head ? bd2 : bc2;
    const float* W3 = head ? Wd3 : Wc3; const float* B3 = head ? bd3 : bc3;

    float h = B1[c];
    #pragma unroll 8
    for (int k = 0; k < 128; k++) h += sroot[k] * W1[k * 64 + c];
    sh1[t] = fmaxf(h, 0.f);
    __syncthreads();

    float h2 = B2[c];
    #pragma unroll 8
    for (int k = 0; k < 64; k++) h2 += sh1[head * 64 + k] * W2[k * 64 + c];
    h2 = fmaxf(h2, 0.f);
    sprod[t] = h2 * W3[c];
    __syncthreads();

    if (c == 0) {
        float s = B3[0];
        #pragma unroll 8
        for (int k = 0; k < 64; k++) s += sprod[head * 64 + k];
        out[head * BSZ + b] = 1.f / (1.f + expf(-s));
    }
}

// ---- launch ----
#define SM_TREE 196608
#define SM_BM   212992
#define SM_EMB  49152

extern "C" void kernel_launch(void* const* d_in, const int* in_sizes, int n_in,
                              void* d_out, int out_size)
{
    const float* op      = (const float*)d_in[0];
    const float* extra   = (const float*)d_in[1];
    const float* cond1   = (const float*)d_in[2];
    const float* cond2   = (const float*)d_in[3];
    const float* bitmap  = (const float*)d_in[4];
    const float* hascond = (const float*)d_in[5];
    const float* W_op = (const float*)d_in[6];   const float* b_op = (const float*)d_in[7];
    const float* W_pr = (const float*)d_in[8];   const float* b_pr = (const float*)d_in[9];
    const float* W_bm = (const float*)d_in[10];  const float* b_bm = (const float*)d_in[11];
    const float* W_r1 = (const float*)d_in[12];  const float* b_r1 = (const float*)d_in[13];
    const float* W_r2 = (const float*)d_in[14];  const float* b_r2 = (const float*)d_in[15];
    const float* W_c1 = (const float*)d_in[16];  const float* b_c1 = (const float*)d_in[17];
    const float* W_c2 = (const float*)d_in[18];  const float* b_c2 = (const float*)d_in[19];
    const float* W_c3 = (const float*)d_in[20];  const float* b_c3 = (const float*)d_in[21];
    const float* W_d1 = (const float*)d_in[22];  const float* b_d1 = (const float*)d_in[23];
    const float* W_d2 = (const float*)d_in[24];  const float* b_d2 = (const float*)d_in[25];
    const float* W_d3 = (const float*)d_in[26];  const float* b_d3 = (const float*)d_in[27];

    cudaFuncSetAttribute(tree_fused_kernel, cudaFuncAttributeMaxDynamicSharedMemorySize, SM_TREE);
    cudaFuncSetAttribute(bm_kernel,         cudaFuncAttributeMaxDynamicSharedMemorySize, SM_BM);
    cudaFuncSetAttribute(embed3_kernel,     cudaFuncAttributeMaxDynamicSharedMemorySize, SM_EMB);

    prep_kernel<<<928, 256>>>(W_r1, W_r2, W_bm, W_op, W_pr);
    embed3_kernel<<<NROWS / 128, 256, SM_EMB>>>(op, extra, cond1, cond2, b_op, b_pr);
    bm_kernel<<<NROWS / 128, 256, SM_BM>>>(bitmap, hascond, b_bm);

    for (int l = 5; l >= 0; --l) {
        int blocks = (BSZ << l) / 128;
        tree_fused_kernel<<<blocks, 512, SM_TREE>>>(b_r1, b_r2, l, (l == 5) ? 4 : 8);
    }

    heads_kernel<<<BSZ, 128>>>(W_c1, b_c1, W_c2, b_c2, W_c3, b_c3,
                               W_d1, b_d1, W_d2, b_d2, W_d3, b_d3,
                               (float*)d_out);
}